// round 7
// baseline (speedup 1.0000x reference)
#include <cuda_runtime.h>
#include <cuda_bf16.h>
#include <cstdint>

// ---------------------------------------------------------------------------
// Problem constants
// ---------------------------------------------------------------------------
#define BATCH     256
#define D_MODEL   2048
#define D_STATE   128
#define D_CONV    4
#define D_SSM     4096
#define NHEADS    64
#define HEADDIM   64
#define CONV_DIM  (D_SSM + 2 * D_STATE)              // 4352
#define D_IN_PROJ (2 * D_SSM + 2 * D_STATE + NHEADS) // 8512

#define OUT_N   (BATCH * D_MODEL)
#define CONV_N  (BATCH * CONV_DIM * D_CONV)
#define SSM_OFF (OUT_N + CONV_N)

// ---------------------------------------------------------------------------
// Scratch (__device__ globals — no allocation allowed)
// ---------------------------------------------------------------------------
__device__ float g_zxbcdt[(size_t)BATCH * D_IN_PROJ];
__device__ float g_act[(size_t)BATCH * CONV_DIM];

// bf16 hi/lo pre-split operands
__device__ __nv_bfloat16 g_ip_hi[(size_t)D_IN_PROJ * D_MODEL];
__device__ __nv_bfloat16 g_ip_lo[(size_t)D_IN_PROJ * D_MODEL];
__device__ __nv_bfloat16 g_op_hi[(size_t)D_MODEL * D_SSM];
__device__ __nv_bfloat16 g_op_lo[(size_t)D_MODEL * D_SSM];
__device__ __nv_bfloat16 g_h_hi[(size_t)BATCH * D_MODEL];
__device__ __nv_bfloat16 g_h_lo[(size_t)BATCH * D_MODEL];
__device__ __nv_bfloat16 g_yz_hi[(size_t)BATCH * D_SSM];
__device__ __nv_bfloat16 g_yz_lo[(size_t)BATCH * D_SSM];

// ---------------------------------------------------------------------------
// PTX helpers
// ---------------------------------------------------------------------------
__device__ __forceinline__ void ldsm4(uint32_t* r, uint32_t addr) {
    asm volatile("ldmatrix.sync.aligned.m8n8.x4.shared.b16 {%0,%1,%2,%3}, [%4];"
                 : "=r"(r[0]), "=r"(r[1]), "=r"(r[2]), "=r"(r[3]) : "r"(addr));
}

__device__ __forceinline__ void mma_bf16(float* d, const uint32_t* a,
                                         const uint32_t* b) {
    asm volatile(
        "mma.sync.aligned.m16n8k16.row.col.f32.bf16.bf16.f32 "
        "{%0,%1,%2,%3}, {%4,%5,%6,%7}, {%8,%9}, {%0,%1,%2,%3};"
        : "+f"(d[0]), "+f"(d[1]), "+f"(d[2]), "+f"(d[3])
        : "r"(a[0]), "r"(a[1]), "r"(a[2]), "r"(a[3]), "r"(b[0]), "r"(b[1]));
}

__device__ __forceinline__ uint32_t smem_u32(const void* p) {
    uint32_t a;
    asm("{ .reg .u64 t; cvta.to.shared.u64 t, %1; cvt.u32.u64 %0, t; }"
        : "=r"(a) : "l"(p));
    return a;
}

__device__ __forceinline__ void cpasync16(uint32_t dst, const void* src) {
    asm volatile("cp.async.cg.shared.global [%0], [%1], 16;"
                 :: "r"(dst), "l"(src));
}
#define CP_COMMIT() asm volatile("cp.async.commit_group;" ::: "memory")
#define CP_WAIT(n)  asm volatile("cp.async.wait_group %0;" :: "n"(n) : "memory")

#define SW128(bo) ((bo) ^ (((bo) >> 3) & 0x70))

// 4 floats -> hi bf16x2-pair + lo bf16x2-pair
__device__ __forceinline__ void split4(const float4& v, uint2& hi, uint2& lo) {
    float f[4] = {v.x, v.y, v.z, v.w};
    uint32_t h[2], l[2];
#pragma unroll
    for (int i = 0; i < 2; i++) {
        uint32_t w;
        asm("cvt.rn.bf16x2.f32 %0, %1, %2;" : "=r"(w) : "f"(f[2*i+1]), "f"(f[2*i]));
        float h0 = __uint_as_float(w << 16);
        float h1 = __uint_as_float(w & 0xffff0000u);
        float l0 = f[2*i]   - h0;
        float l1 = f[2*i+1] - h1;
        uint32_t wl;
        asm("cvt.rn.bf16x2.f32 %0, %1, %2;" : "=r"(wl) : "f"(l1), "f"(l0));
        h[i] = w; l[i] = wl;
    }
    hi = make_uint2(h[0], h[1]);
    lo = make_uint2(l[0], l[1]);
}

// ---------------------------------------------------------------------------
// fp32 -> bf16 hi/lo split kernel
// ---------------------------------------------------------------------------
__global__ __launch_bounds__(256) void split_kernel(
    const float4* __restrict__ in, uint2* __restrict__ hi,
    uint2* __restrict__ lo, int n4)
{
    int i = blockIdx.x * 256 + threadIdx.x;
    if (i >= n4) return;
    uint2 h, l;
    split4(in[i], h, l);
    hi[i] = h;
    lo[i] = l;
}

// ---------------------------------------------------------------------------
// bf16 tensor-core GEMM (3-term split), cp.async 2-stage pipeline.
// C[M,N] = A[M,K] @ B[N,K]^T; A,B pre-split bf16 hi/lo (K-major).
// CTA tile 256x64 (M=whole batch -> single wave), BK=64 (one SW128 row).
// 256 thr = 8 warps, warp grid 4(M) x 2(N), 64x32 per warp.
// Stage: Ahi 32K | Alo 32K | Bhi 8K | Blo 8K = 80 KB; 2 stages = 160 KB dyn.
// ---------------------------------------------------------------------------
#define BKC 64
#define STG 81920
#define ST_AHI 0
#define ST_ALO 32768
#define ST_BHI 65536
#define ST_BLO 73728
#define GEMM_SMEM (2 * STG)

template <bool ATOMIC>
__global__ __launch_bounds__(256) void gemm_bf16_tc(
    const __nv_bfloat16* __restrict__ Ahi, const __nv_bfloat16* __restrict__ Alo,
    const __nv_bfloat16* __restrict__ Bhi, const __nv_bfloat16* __restrict__ Blo,
    float* __restrict__ C, int M, int N, int K, int klen)
{
    extern __shared__ __align__(1024) char sm[];
    const uint32_t sb = smem_u32(sm);

    const int tid  = threadIdx.x;
    const int lane = tid & 31;
    const int warp = tid >> 5;
    const int n0 = blockIdx.x * 64;
    const int m0 = blockIdx.y * 256;
    const int k0 = blockIdx.z * klen;
    const int wm = warp >> 1;      // 0..3  (64-row slab)
    const int wn = warp & 1;       // 0..1  (32-col slab)

    // ---- async-copy mapping ----
    // A: 256 rows x 8 granules(16B) = 2048 -> 8 per thread
    // B:  64 rows x 8 granules      =  512 -> 2 per thread
    const int a_r0 = tid >> 3;          // rows a_r0, a_r0+32, ... (stride 32)
    const int a_g  = tid & 7;
    const uint32_t a_sw0 = SW128((uint32_t)(a_r0 * 128 + a_g * 16));
    const __nv_bfloat16* a_src0 = Ahi + (size_t)(m0 + a_r0) * K + k0 + a_g * 8;
    const size_t aStride = (size_t)32 * K;          // +32 rows

    const int b_r0 = tid >> 3;
    const uint32_t b_sw0 = SW128((uint32_t)(b_r0 * 128 + a_g * 16));
    const __nv_bfloat16* b_src0 = Bhi + (size_t)(n0 + b_r0) * K + k0 + a_g * 8;

    const ptrdiff_t dAL = Alo - Ahi;
    const ptrdiff_t dBL = Blo - Bhi;

    // ---- ldmatrix lane addressing ----
    const int g4 = lane >> 3;
    const uint32_t xm = (uint32_t)(lane & 7) << 4;      // swizzle term

    const int ra = wm * 64 + ((g4 & 1) << 3) + (lane & 7);
    const uint32_t a_row  = (uint32_t)(ra * 128);
    const uint32_t a_koff = (uint32_t)(g4 >> 1) << 4;

    const int rb = wn * 32 + ((g4 >> 1) << 3) + (lane & 7);
    const uint32_t b_row  = (uint32_t)(rb * 128);
    const uint32_t b_koff = (uint32_t)(g4 & 1) << 4;

    float acc[4][4][4];
#pragma unroll
    for (int i = 0; i < 4; i++)
#pragma unroll
        for (int j = 0; j < 4; j++)
#pragma unroll
            for (int v = 0; v < 4; v++) acc[i][j][v] = 0.0f;

    const int nch = klen / BKC;

    // ---- issue stage 0 ----
    {
        const uint32_t s0 = sb;
        const __nv_bfloat16* ap = a_src0;
#pragma unroll
        for (int q = 0; q < 8; q++) {
            uint32_t off = a_sw0 + q * 4096;          // +32 rows = 4096B
            cpasync16(s0 + ST_AHI + off, ap);
            cpasync16(s0 + ST_ALO + off, ap + dAL);
            ap += aStride;
        }
        const __nv_bfloat16* bp = b_src0;
#pragma unroll
        for (int q = 0; q < 2; q++) {
            uint32_t off = b_sw0 + q * 4096;
            cpasync16(s0 + ST_BHI + off, bp);
            cpasync16(s0 + ST_BLO + off, bp + dBL);
            bp += aStride;
        }
        CP_COMMIT();
    }

    for (int c = 0; c < nch; c++) {
        if (c + 1 < nch) {
            const uint32_t sn = sb + ((c + 1) & 1) * STG;
            const int koff = (c + 1) * BKC;
            const __nv_bfloat16* ap = a_src0 + koff;
#pragma unroll
            for (int q = 0; q < 8; q++) {
                uint32_t off = a_sw0 + q * 4096;
                cpasync16(sn + ST_AHI + off, ap);
                cpasync16(sn + ST_ALO + off, ap + dAL);
                ap += aStride;
            }
            const __nv_bfloat16* bp = b_src0 + koff;
#pragma unroll
            for (int q = 0; q < 2; q++) {
                uint32_t off = b_sw0 + q * 4096;
                cpasync16(sn + ST_BHI + off, bp);
                cpasync16(sn + ST_BLO + off, bp + dBL);
                bp += aStride;
            }
            CP_COMMIT();
            CP_WAIT(1);
        } else {
            CP_WAIT(0);
        }
        __syncthreads();

        const uint32_t ss = sb + (c & 1) * STG;
        const uint32_t a_base = ss + ST_AHI + a_row;
        const uint32_t b_base = ss + ST_BHI + b_row;

#pragma unroll
        for (int ks = 0; ks < 4; ks++) {
            const uint32_t ak = ((uint32_t)(32 * ks) | a_koff) ^ xm;
            const uint32_t bk = ((uint32_t)(32 * ks) | b_koff) ^ xm;

            uint32_t bh[2][4], bl[2][4];
#pragma unroll
            for (int jj = 0; jj < 2; jj++) {
                uint32_t bd = b_base + jj * 2048 + bk;
                ldsm4(bh[jj], bd);
                ldsm4(bl[jj], bd + (ST_BLO - ST_BHI));
            }
#pragma unroll
            for (int i = 0; i < 4; i++) {
                uint32_t ah[4], al[4];
                uint32_t ad = a_base + i * 2048 + ak;
                ldsm4(ah, ad);
                ldsm4(al, ad + (ST_ALO - ST_AHI));
#pragma unroll
                for (int j = 0; j < 4; j++) {
                    const uint32_t* Bh = &bh[j >> 1][(j & 1) * 2];
                    const uint32_t* Bl = &bl[j >> 1][(j & 1) * 2];
                    mma_bf16(acc[i][j], ah, Bh);   // hi*hi
                    mma_bf16(acc[i][j], al, Bh);   // lo*hi
                    mma_bf16(acc[i][j], ah, Bl);   // hi*lo
                }
            }
        }
        __syncthreads();
    }

    // ---- epilogue ----
#pragma unroll
    for (int i = 0; i < 4; i++) {
#pragma unroll
        for (int j = 0; j < 4; j++) {
            int row = m0 + wm * 64 + i * 16 + (lane >> 2);
            int col = n0 + wn * 32 + j * 8 + (lane & 3) * 2;
            size_t o0 = (size_t)row * N + col;
            size_t o1 = (size_t)(row + 8) * N + col;
            if (ATOMIC) {
                atomicAdd(&C[o0],     acc[i][j][0]);
                atomicAdd(&C[o0 + 1], acc[i][j][1]);
                atomicAdd(&C[o1],     acc[i][j][2]);
                atomicAdd(&C[o1 + 1], acc[i][j][3]);
            } else {
                *(float2*)(C + o0) = make_float2(acc[i][j][0], acc[i][j][1]);
                *(float2*)(C + o1) = make_float2(acc[i][j][2], acc[i][j][3]);
            }
        }
    }
}

// ---------------------------------------------------------------------------
// Conv step
// ---------------------------------------------------------------------------
__global__ __launch_bounds__(256) void conv_kernel(
    const float* __restrict__ conv_in,
    const float* __restrict__ conv_w,
    const float* __restrict__ conv_b,
    float* __restrict__ conv_out)
{
    const int c = blockIdx.x * 256 + threadIdx.x;
    const int b = blockIdx.y;
    const size_t idx = (size_t)b * CONV_DIM + c;

    float4 s = *(const float4*)(conv_in + idx * 4);
    float4 w = *(const float4*)(conv_w + (size_t)c * 4);
    float xin = g_zxbcdt[(size_t)b * D_IN_PROJ + D_SSM + c];

    float v = s.y * w.x + s.z * w.y + s.w * w.z + xin * w.w + conv_b[c];
    float act = v / (1.0f + expf(-v));

    *(float4*)(conv_out + idx * 4) = make_float4(s.y, s.z, s.w, xin);
    g_act[idx] = act;
}

// ---------------------------------------------------------------------------
// SSM fused kernel — writes yz directly as bf16 hi/lo for out_proj
// ---------------------------------------------------------------------------
__global__ __launch_bounds__(256) void ssm_kernel(
    const float* __restrict__ ssm_in,
    const float* __restrict__ dt_bias,
    const float* __restrict__ A_log,
    const float* __restrict__ Dvec,
    float* __restrict__ ssm_out)
{
    const int h = blockIdx.x;
    const int b = blockIdx.y;
    const int tid = threadIdx.x;

    __shared__ __align__(16) float sB[D_STATE];
    __shared__ __align__(16) float sC[D_STATE];
    __shared__ float s_dt, s_dA, s_Dh;

    if (tid == 0) {
        float v = g_zxbcdt[(size_t)b * D_IN_PROJ + (2 * D_SSM + 2 * D_STATE) + h]
                  + dt_bias[h];
        float dt = fmaxf(v, 0.0f) + log1pf(expf(-fabsf(v)));
        float A  = -expf(A_log[h]);
        s_dt = dt;
        s_dA = expf(dt * A);
        s_Dh = Dvec[h];
    }
    if (tid < D_STATE) {
        sB[tid] = g_act[(size_t)b * CONV_DIM + D_SSM + tid];
        sC[tid] = g_act[(size_t)b * CONV_DIM + D_SSM + D_STATE + tid];
    }
    __syncthreads();

    const float dt = s_dt, dA = s_dA, Dh = s_Dh;
    const int warp = tid >> 5, lane = tid & 31;

    const float* base_in  = ssm_in  + (((size_t)b * NHEADS + h) * HEADDIM) * D_STATE;
    float*       base_out = ssm_out + (((size_t)b * NHEADS + h) * HEADDIM) * D_STATE;

    const float4 bbv = *(const float4*)&sB[lane * 4];
    const float4 ccv = *(const float4*)&sC[lane * 4];

#pragma unroll
    for (int r = 0; r < 8; r++) {
        const int p = warp * 8 + r;
        float x = g_act[(size_t)b * CONV_DIM + h * HEADDIM + p];
        float xdt = x * dt;

        float4 st = *(const float4*)(base_in + (size_t)p * D_STATE + lane * 4);
        float n0 = st.x * dA + bbv.x * xdt;
        float n1 = st.y * dA + bbv.y * xdt;
        float n2 = st.z * dA + bbv.z * xdt;
        float n3 = st.w * dA + bbv.w * xdt;
        *(float4*)(base_out + (size_t)p * D_STATE + lane * 4) =
            make_float4(n0, n1, n2, n3);

        float ysum = n0 * ccv.x + n1 * ccv.y + n2 * ccv.z + n3 * ccv.w;
#pragma unroll
        for (int off = 16; off; off >>= 1)
            ysum += __shfl_xor_sync(0xffffffffu, ysum, off);

        if (lane == 0) {
            float y = ysum + Dh * x;
            float z = g_zxbcdt[(size_t)b * D_IN_PROJ + h * HEADDIM + p];
            float sz = z / (1.0f + expf(-z));
            float yz = y * sz;
            size_t oy = (size_t)b * D_SSM + h * HEADDIM + p;
            __nv_bfloat16 hb = __float2bfloat16(yz);
            float hf = __bfloat162float(hb);
            g_yz_hi[oy] = hb;
            g_yz_lo[oy] = __float2bfloat16(yz - hf);
        }
    }
}

__global__ __launch_bounds__(256) void zero_kernel(float4* __restrict__ p, int n4) {
    int i = blockIdx.x * 256 + threadIdx.x;
    if (i < n4) p[i] = make_float4(0.f, 0.f, 0.f, 0.f);
}

// ---------------------------------------------------------------------------
// Launch
// ---------------------------------------------------------------------------
extern "C" void kernel_launch(void* const* d_in, const int* in_sizes, int n_in,
                              void* d_out, int out_size)
{
    const float* hidden    = (const float*)d_in[0];
    const float* conv_in   = (const float*)d_in[1];
    const float* ssm_in    = (const float*)d_in[2];
    const float* in_proj_w = (const float*)d_in[3];
    const float* conv_w    = (const float*)d_in[4];
    const float* conv_b    = (const float*)d_in[5];
    const float* dt_bias   = (const float*)d_in[6];
    const float* A_log     = (const float*)d_in[7];
    const float* Dvec      = (const float*)d_in[8];
    const float* out_w     = (const float*)d_in[9];

    float* out_p  = (float*)d_out;
    float* conv_p = out_p + OUT_N;
    float* ssm_p  = out_p + SSM_OFF;

    float* zx; cudaGetSymbolAddress((void**)&zx, g_zxbcdt);
    __nv_bfloat16 *ip_hi, *ip_lo, *op_hi, *op_lo, *h_hi, *h_lo, *yz_hi, *yz_lo;
    cudaGetSymbolAddress((void**)&ip_hi, g_ip_hi);
    cudaGetSymbolAddress((void**)&ip_lo, g_ip_lo);
    cudaGetSymbolAddress((void**)&op_hi, g_op_hi);
    cudaGetSymbolAddress((void**)&op_lo, g_op_lo);
    cudaGetSymbolAddress((void**)&h_hi, g_h_hi);
    cudaGetSymbolAddress((void**)&h_lo, g_h_lo);
    cudaGetSymbolAddress((void**)&yz_hi, g_yz_hi);
    cudaGetSymbolAddress((void**)&yz_lo, g_yz_lo);

    static bool attr_set = false;
    if (!attr_set) {
        cudaFuncSetAttribute(gemm_bf16_tc<false>,
            cudaFuncAttributeMaxDynamicSharedMemorySize, GEMM_SMEM);
        cudaFuncSetAttribute(gemm_bf16_tc<true>,
            cudaFuncAttributeMaxDynamicSharedMemorySize, GEMM_SMEM);
        attr_set = true;
    }

    // 0) zero out-proj output region (split-K atomics accumulate into it)
    zero_kernel<<<(OUT_N / 4 + 255) / 256, 256>>>((float4*)out_p, OUT_N / 4);

    // 0b) pre-split operands to bf16 hi/lo
    {
        int n4 = BATCH * D_MODEL / 4;
        split_kernel<<<(n4 + 255) / 256, 256>>>(
            (const float4*)hidden, (uint2*)h_hi, (uint2*)h_lo, n4);
    }
    {
        int n4 = D_IN_PROJ * D_MODEL / 4;
        split_kernel<<<(n4 + 255) / 256, 256>>>(
            (const float4*)in_proj_w, (uint2*)ip_hi, (uint2*)ip_lo, n4);
    }
    {
        int n4 = D_MODEL * D_SSM / 4;
        split_kernel<<<(n4 + 255) / 256, 256>>>(
            (const float4*)out_w, (uint2*)op_hi, (uint2*)op_lo, n4);
    }

    // 1) in_proj: zxbcdt[256,8512] = hidden @ in_proj_w^T  (single wave, 133 CTAs)
    {
        dim3 grid(D_IN_PROJ / 64, BATCH / 256, 1);    // (133, 1, 1)
        gemm_bf16_tc<false><<<grid, 256, GEMM_SMEM>>>(
            h_hi, h_lo, ip_hi, ip_lo, zx,
            BATCH, D_IN_PROJ, D_MODEL, D_MODEL);
    }

    // 2) conv step
    {
        dim3 grid(CONV_DIM / 256, BATCH, 1);
        conv_kernel<<<grid, 256>>>(conv_in, conv_w, conv_b, conv_p);
    }

    // 3) fused SSM update + y*silu(z) (emits bf16 hi/lo yz)
    {
        dim3 grid(NHEADS, BATCH, 1);
        ssm_kernel<<<grid, 256>>>(ssm_in, dt_bias, A_log, Dvec, ssm_p);
    }

    // 4) out_proj: out[256,2048] = yz @ out_w^T  (split-K=4 -> 128 CTAs, atomic)
    {
        dim3 grid(D_MODEL / 64, BATCH / 256, 4);      // (32, 1, 4)
        gemm_bf16_tc<true><<<grid, 256, GEMM_SMEM>>>(
            yz_hi, yz_lo, op_hi, op_lo, out_p,
            BATCH, D_MODEL, D_SSM, D_SSM / 4);
    }
}